// round 4
// baseline (speedup 1.0000x reference)
#include <cuda_runtime.h>
#include <cstdint>

// Problem constants (FrustumPooling_721554506291)
#define Bb 2
#define Nn 4
#define Dd 48
#define Hh 28
#define Ww 60
#define Cc 64
#define NX 192
#define NY 192
#define PLANE (NY*NX)                  // 36864
#define OUT_ELEMS (Bb*Cc*PLANE)        // 4,718,592 floats
#define NGROUPS (Bb*Dd*Ww)             // 5760 columns (one 16-lane group each)

static_assert(NGROUPS % 16 == 0, "grid must divide evenly");

// Per-(b,n): combine[9] followed by trans[3]
__device__ float g_combine[Bb*Nn*12];

// ---------------------------------------------------------------------------
// Setup: combine = rots @ inv(K), trans = pose[:3,3]
// ---------------------------------------------------------------------------
__global__ void setup_kernel(const float* __restrict__ intr,
                             const float* __restrict__ pose)
{
    int i = threadIdx.x;
    if (i >= Bb*Nn) return;
    const float* K = intr + i*9;
    const float* P = pose + i*16;

    float a=K[0], b=K[1], c=K[2];
    float d=K[3], e=K[4], f=K[5];
    float g=K[6], h=K[7], ii=K[8];
    float A0 =  (e*ii - f*h);
    float A1 = -(d*ii - f*g);
    float A2 =  (d*h  - e*g);
    float det = a*A0 + b*A1 + c*A2;
    float id  = 1.0f / det;
    float inv[9];
    inv[0] = A0*id;           inv[1] = (c*h - b*ii)*id; inv[2] = (b*f - c*e)*id;
    inv[3] = A1*id;           inv[4] = (a*ii - c*g)*id; inv[5] = (c*d - a*f)*id;
    inv[6] = A2*id;           inv[7] = (b*g - a*h)*id;  inv[8] = (a*e - b*d)*id;

    float* out = g_combine + i*12;
    #pragma unroll
    for (int r = 0; r < 3; r++) {
        #pragma unroll
        for (int col = 0; col < 3; col++) {
            out[r*3+col] = P[r*4+0]*inv[0*3+col]
                         + P[r*4+1]*inv[1*3+col]
                         + P[r*4+2]*inv[2*3+col];
        }
        out[9+r] = P[r*4+3];
    }
}

// ---------------------------------------------------------------------------
// Zero the output (float4 stores); output is poisoned by the harness.
// ---------------------------------------------------------------------------
__global__ void zero_out_kernel(float4* __restrict__ o)
{
    int i = blockIdx.x * blockDim.x + threadIdx.x;
    if (i < OUT_ELEMS/4)
        o[i] = make_float4(0.f, 0.f, 0.f, 0.f);
}

__device__ __forceinline__ void red1(float* addr, float v)
{
    asm volatile("red.global.add.f32 [%0], %1;" :: "l"(addr), "f"(v) : "memory");
}

// Flush one merged accumulator: 4 scalar reds into [b][c][y][x] layout.
__device__ __forceinline__ void flush4(float* __restrict__ out,
                                       int baseBC, int pos, float4 a)
{
    float* p = out + baseBC + pos;
    red1(p,           a.x);
    red1(p +   PLANE, a.y);
    red1(p + 2*PLANE, a.z);
    red1(p + 3*PLANE, a.w);
}

// ---------------------------------------------------------------------------
// Column scatter: one 16-lane group per (b,d,w) column. Loops n (outer) and
// h (inner); computes the target cell per iteration and merges consecutive
// equal cells in registers, flushing red.global.add.f32 only on change.
// Generic for any pose/intrinsics; collapses ~112x for this input.
// ---------------------------------------------------------------------------
__global__ void __launch_bounds__(256)
scatter_kernel(const float* __restrict__ x, float* __restrict__ out)
{
    __shared__ float s_cm[Bb*Nn*12];     // 96 floats
    int tid = threadIdx.x;
    if (tid < Bb*Nn*12) s_cm[tid] = g_combine[tid];
    __syncthreads();

    int g     = blockIdx.x * 16 + (tid >> 4);
    int lane4 = (tid & 15) * 4;

    int w  = g % Ww;  int t2 = g / Ww;
    int d  = t2 % Dd;
    int b  = t2 / Dd;

    float u  = (float)w * (479.0f/59.0f);
    float df = 2.0f + (float)d;
    float ud = u * df;

    int baseBC = (b*Cc + lane4) * PLANE;
    const float* xb = x + ((size_t)(b*Nn)*Dd + d) * (Hh*Ww*Cc)
                        + w*Cc + lane4;

    int    run = -1;
    float4 acc = make_float4(0.f, 0.f, 0.f, 0.f);

    #pragma unroll
    for (int n = 0; n < Nn; n++) {
        const float* cm = s_cm + (b*Nn + n)*12;
        // loop-invariant parts (h enters only via vd)
        float p0 = cm[0]*ud + cm[2]*df + cm[9];
        float p1 = cm[3]*ud + cm[5]*df + cm[10];
        float p2 = cm[6]*ud + cm[8]*df + cm[11];
        float s0 = cm[1], s1 = cm[4], s2 = cm[7];
        const float* xn = xb + n*(Dd*Hh*Ww*Cc);

        #pragma unroll 4
        for (int h = 0; h < Hh; h++) {
            float vd = ((float)h * (223.0f/27.0f)) * df;
            float g0 = p0 + s0*vd;
            float g1 = p1 + s1*vd;
            float g2 = p2 + s2*vd;

            int gx = (int)(g0 * 4.0f + 96.0f);   // trunc-toward-zero == astype(int32)
            int gy = (int)(g1 * 4.0f + 96.0f);
            int gz = (int)((g2 + 10.0f) / 20.0f);

            bool kept = ((unsigned)gx < NX) && ((unsigned)gy < NY) && (gz == 0);
            if (kept) {
                float4 val = *reinterpret_cast<const float4*>(xn + h*(Ww*Cc));
                int pos = gy*NX + gx;
                if (pos == run) {
                    acc.x += val.x; acc.y += val.y;
                    acc.z += val.z; acc.w += val.w;
                } else {
                    if (run >= 0) flush4(out, baseBC, run, acc);
                    run = pos;
                    acc = val;
                }
            }
        }
    }
    if (run >= 0) flush4(out, baseBC, run, acc);
}

// ---------------------------------------------------------------------------
extern "C" void kernel_launch(void* const* d_in, const int* in_sizes, int n_in,
                              void* d_out, int out_size)
{
    const float* x    = (const float*)d_in[0];
    const float* intr = (const float*)d_in[1];
    const float* pose = (const float*)d_in[2];
    float* out = (float*)d_out;

    setup_kernel<<<1, 32>>>(intr, pose);
    zero_out_kernel<<<(OUT_ELEMS/4 + 255)/256, 256>>>((float4*)out);
    scatter_kernel<<<NGROUPS/16, 256>>>(x, out);
}

// round 5
// speedup vs baseline: 1.3152x; 1.3152x over previous
#include <cuda_runtime.h>
#include <cstdint>

// Problem constants (FrustumPooling_721554506291)
#define Bb 2
#define Nn 4
#define Dd 48
#define Hh 28
#define Ww 60
#define Cc 64
#define NX 192
#define NY 192
#define PLANE (NY*NX)                  // 36864
#define OUT_ELEMS (Bb*Cc*PLANE)        // 4,718,592 floats
#define NBLOCKS (Bb*Dd*Ww)             // 5760 columns, one block each
#define NPAIRS (Nn*Hh)                 // 112 (n,h) vectors per column

// ---------------------------------------------------------------------------
// Zero the output (float4 stores); harness poisons d_out.
// ---------------------------------------------------------------------------
__global__ void zero_out_kernel(float4* __restrict__ o)
{
    int i = blockIdx.x * blockDim.x + threadIdx.x;
    if (i < OUT_ELEMS/4)
        o[i] = make_float4(0.f, 0.f, 0.f, 0.f);
}

__device__ __forceinline__ void red1(float* addr, float v)
{
    asm volatile("red.global.add.f32 [%0], %1;" :: "l"(addr), "f"(v) : "memory");
}

// ---------------------------------------------------------------------------
// Column scatter, block-per-column:
//   grid = (b,d,w) columns; block = 256 threads = 8 warps.
//   Warp wi covers pairs j = wi, wi+8, ... (14 of the 112 (n,h) vectors).
//   Lane owns channels (2*lane, 2*lane+1): one float2 load per vector.
//   Consecutive equal cells are merged in registers; each flush issues
//   2 scalar red.global.add.f32 directly into the final [b][c][y][x] layout.
//   Setup (combine = rots @ inv(K)) is folded in: 8 threads per block.
// ---------------------------------------------------------------------------
__global__ void __launch_bounds__(256)
scatter_kernel(const float* __restrict__ x,
               const float* __restrict__ intr,
               const float* __restrict__ pose,
               float* __restrict__ out)
{
    __shared__ float s_cm[Bb*Nn*12];     // combine[9] + trans[3] per (b,n)

    int tid = threadIdx.x;

    // ---- folded setup: 8 threads compute the 8 combine matrices ----
    if (tid < Bb*Nn) {
        const float* K = intr + tid*9;
        const float* P = pose + tid*16;

        float a=K[0], b=K[1], c=K[2];
        float d=K[3], e=K[4], f=K[5];
        float g=K[6], h=K[7], ii=K[8];
        float A0 =  (e*ii - f*h);
        float A1 = -(d*ii - f*g);
        float A2 =  (d*h  - e*g);
        float det = a*A0 + b*A1 + c*A2;
        float id  = 1.0f / det;
        float inv[9];
        inv[0] = A0*id;           inv[1] = (c*h - b*ii)*id; inv[2] = (b*f - c*e)*id;
        inv[3] = A1*id;           inv[4] = (a*ii - c*g)*id; inv[5] = (c*d - a*f)*id;
        inv[6] = A2*id;           inv[7] = (b*g - a*h)*id;  inv[8] = (a*e - b*d)*id;

        float* o = s_cm + tid*12;
        #pragma unroll
        for (int r = 0; r < 3; r++) {
            #pragma unroll
            for (int col = 0; col < 3; col++) {
                o[r*3+col] = P[r*4+0]*inv[0*3+col]
                           + P[r*4+1]*inv[1*3+col]
                           + P[r*4+2]*inv[2*3+col];
            }
            o[9+r] = P[r*4+3];
        }
    }
    __syncthreads();

    // ---- column decode ----
    int g  = blockIdx.x;
    int w  = g % Ww;  int t2 = g / Ww;
    int d  = t2 % Dd;
    int b  = t2 / Dd;

    float u  = (float)w * (479.0f/59.0f);
    float df = 2.0f + (float)d;
    float ud = u * df;

    int wi   = tid >> 5;          // warp 0..7
    int lane = tid & 31;          // owns channels 2*lane, 2*lane+1

    int   base   = (b*Cc + 2*lane) * PLANE;
    const float* xcol = x + ((size_t)(b*Nn)*Dd + d) * (Hh*Ww*Cc)
                          + w*Cc + 2*lane;

    int    run = -1;
    float2 acc = make_float2(0.f, 0.f);

    #pragma unroll
    for (int jj = 0; jj < NPAIRS/8; jj++) {       // 14 iterations
        int j = wi + jj*8;
        int n = j / Hh;
        int h = j - n*Hh;

        const float* cm = s_cm + (b*Nn + n)*12;
        float vd = ((float)h * (223.0f/27.0f)) * df;
        float g0 = cm[0]*ud + cm[2]*df + cm[9]  + cm[1]*vd;
        float g1 = cm[3]*ud + cm[5]*df + cm[10] + cm[4]*vd;
        float g2 = cm[6]*ud + cm[8]*df + cm[11] + cm[7]*vd;

        int gx = (int)(g0 * 4.0f + 96.0f);   // trunc-toward-zero == astype(int32)
        int gy = (int)(g1 * 4.0f + 96.0f);
        int gz = (int)((g2 + 10.0f) / 20.0f);

        bool kept = ((unsigned)gx < NX) && ((unsigned)gy < NY) && (gz == 0);
        if (kept) {
            float2 val = *reinterpret_cast<const float2*>(
                xcol + ((size_t)n*(Dd*Hh*Ww) + h*Ww) * Cc);
            int pos = gy*NX + gx;
            if (pos == run) {
                acc.x += val.x; acc.y += val.y;
            } else {
                if (run >= 0) {
                    red1(out + base + run,         acc.x);
                    red1(out + base + PLANE + run, acc.y);
                }
                run = pos;
                acc = val;
            }
        }
    }
    if (run >= 0) {
        red1(out + base + run,         acc.x);
        red1(out + base + PLANE + run, acc.y);
    }
}

// ---------------------------------------------------------------------------
extern "C" void kernel_launch(void* const* d_in, const int* in_sizes, int n_in,
                              void* d_out, int out_size)
{
    const float* x    = (const float*)d_in[0];
    const float* intr = (const float*)d_in[1];
    const float* pose = (const float*)d_in[2];
    float* out = (float*)d_out;

    zero_out_kernel<<<(OUT_ELEMS/4 + 255)/256, 256>>>((float4*)out);
    scatter_kernel<<<NBLOCKS, 256>>>(x, intr, pose, out);
}

// round 7
// speedup vs baseline: 2.1965x; 1.6701x over previous
#include <cuda_runtime.h>
#include <cstdint>

// Problem constants (FrustumPooling_721554506291)
#define Bb 2
#define Nn 4
#define Dd 48
#define Hh 28
#define Ww 60
#define Cc 64
#define NX 192
#define NY 192
#define PLANE (NY*NX)                  // 36864
#define OUT_ELEMS (Bb*Cc*PLANE)        // 4,718,592 floats
#define NBLOCKS (Bb*Dd*Ww)             // 5760 columns, one block each
#define NPAIRS (Nn*Hh)                 // 112 (n,h) vectors per column
#define PER_WARP (NPAIRS/8)            // 14 pairs per warp

static_assert(NPAIRS % 8 == 0, "pairs must split across 8 warps");

// ---------------------------------------------------------------------------
// Zero the output (float4 stores); harness poisons d_out.
// ---------------------------------------------------------------------------
__global__ void zero_out_kernel(float4* __restrict__ o)
{
    int i = blockIdx.x * blockDim.x + threadIdx.x;
    if (i < OUT_ELEMS/4)
        o[i] = make_float4(0.f, 0.f, 0.f, 0.f);
}

__device__ __forceinline__ void red1(float* addr, float v)
{
    asm volatile("red.global.add.f32 [%0], %1;" :: "l"(addr), "f"(v) : "memory");
}

// ---------------------------------------------------------------------------
// Column scatter, block-per-(b,d,w):
//   Setup:   8 threads build combine = rots @ inv(K) in smem.
//   Phase A: 112 threads compute (cell, x-offset) per (n,h) pair -> smem.
//   Phase B: 8 warps x 14 contiguous pairs; lane owns channels 2l,2l+1.
//            Consecutive equal cells merge in registers; run changes flush
//            directly; FINAL runs are merged block-wide in smem so the
//            common case issues one red set per block, not per warp.
// ---------------------------------------------------------------------------
__global__ void __launch_bounds__(256)
scatter_kernel(const float* __restrict__ x,
               const float* __restrict__ intr,
               const float* __restrict__ pose,
               float* __restrict__ out)
{
    __shared__ float s_cm[Bb*Nn*12];       // combine[9]+trans[3] per (b,n)
    __shared__ int2  s_pair[NPAIRS];       // (cell, xoff) per pair, cell=-1 if rejected
    __shared__ int   s_run[8];             // final run per warp
    __shared__ float s_acc[8][Cc];         // final acc per warp per channel

    int tid = threadIdx.x;

    // ---- setup: 8 threads compute the combine matrices ----
    if (tid < Bb*Nn) {
        const float* K = intr + tid*9;
        const float* P = pose + tid*16;

        float a=K[0], b=K[1], c=K[2];
        float d=K[3], e=K[4], f=K[5];
        float g=K[6], h=K[7], ii=K[8];
        float A0 =  (e*ii - f*h);
        float A1 = -(d*ii - f*g);
        float A2 =  (d*h  - e*g);
        float det = a*A0 + b*A1 + c*A2;
        float id  = 1.0f / det;
        float inv[9];
        inv[0] = A0*id;           inv[1] = (c*h - b*ii)*id; inv[2] = (b*f - c*e)*id;
        inv[3] = A1*id;           inv[4] = (a*ii - c*g)*id; inv[5] = (c*d - a*f)*id;
        inv[6] = A2*id;           inv[7] = (b*g - a*h)*id;  inv[8] = (a*e - b*d)*id;

        float* o = s_cm + tid*12;
        #pragma unroll
        for (int r = 0; r < 3; r++) {
            #pragma unroll
            for (int col = 0; col < 3; col++) {
                o[r*3+col] = P[r*4+0]*inv[0*3+col]
                           + P[r*4+1]*inv[1*3+col]
                           + P[r*4+2]*inv[2*3+col];
            }
            o[9+r] = P[r*4+3];
        }
    }
    __syncthreads();

    // ---- column decode ----
    int gcol = blockIdx.x;
    int w  = gcol % Ww;  int t2 = gcol / Ww;
    int d  = t2 % Dd;
    int b  = t2 / Dd;

    float u  = (float)w * (479.0f/59.0f);
    float df = 2.0f + (float)d;
    float ud = u * df;

    // ---- Phase A: one thread per (n,h) pair ----
    if (tid < NPAIRS) {
        int n = tid / Hh;
        int h = tid - n*Hh;

        const float* cm = s_cm + (b*Nn + n)*12;
        float vd = ((float)h * (223.0f/27.0f)) * df;
        float g0 = cm[0]*ud + cm[2]*df + cm[9]  + cm[1]*vd;
        float g1 = cm[3]*ud + cm[5]*df + cm[10] + cm[4]*vd;
        float g2 = cm[6]*ud + cm[8]*df + cm[11] + cm[7]*vd;

        int gx = (int)(g0 * 4.0f + 96.0f);   // trunc-toward-zero == astype(int32)
        int gy = (int)(g1 * 4.0f + 96.0f);
        int gz = (int)((g2 + 10.0f) / 20.0f);

        bool kept = ((unsigned)gx < NX) && ((unsigned)gy < NY) && (gz == 0);
        int cell = kept ? (gy*NX + gx) : -1;
        int xoff = (n*(Dd*Hh*Ww) + h*Ww) * Cc;
        s_pair[tid] = make_int2(cell, xoff);
    }
    __syncthreads();

    // ---- Phase B: 8 warps, contiguous 14-pair chunks ----
    int wi   = tid >> 5;
    int lane = tid & 31;

    int   base = (b*Cc + 2*lane) * PLANE;
    const float* xcol = x + ((size_t)(b*Nn)*Dd + d) * (Hh*Ww*Cc)
                          + w*Cc + 2*lane;

    int    run = -1;
    float2 acc = make_float2(0.f, 0.f);

    #pragma unroll
    for (int jj = 0; jj < PER_WARP; jj++) {
        int2 pr = s_pair[wi*PER_WARP + jj];
        if (pr.x >= 0) {
            float2 val = *reinterpret_cast<const float2*>(xcol + pr.y);
            if (pr.x == run) {
                acc.x += val.x; acc.y += val.y;
            } else {
                if (run >= 0) {     // mid-loop flush (rare)
                    red1(out + base + run,         acc.x);
                    red1(out + base + PLANE + run, acc.y);
                }
                run = pr.x;
                acc = val;
            }
        }
    }

    // ---- block-wide merge of final runs ----
    if (lane == 0) s_run[wi] = run;
    s_acc[wi][2*lane]   = acc.x;
    s_acc[wi][2*lane+1] = acc.y;
    __syncthreads();

    if (tid < Cc) {          // 64 threads, one channel each
        int   c     = tid;
        float* outc = out + ((size_t)b*Cc + c) * PLANE;
        #pragma unroll
        for (int i = 0; i < 8; i++) {
            int r = s_run[i];
            if (r < 0) continue;
            bool first = true;
            #pragma unroll
            for (int j = 0; j < 8; j++)
                if (j < i && s_run[j] == r) first = false;
            if (!first) continue;
            float sum = s_acc[i][c];
            #pragma unroll
            for (int j = 0; j < 8; j++)
                if (j > i && s_run[j] == r) sum += s_acc[j][c];
            red1(outc + r, sum);
        }
    }
}

// ---------------------------------------------------------------------------
extern "C" void kernel_launch(void* const* d_in, const int* in_sizes, int n_in,
                              void* d_out, int out_size)
{
    const float* x    = (const float*)d_in[0];
    const float* intr = (const float*)d_in[1];
    const float* pose = (const float*)d_in[2];
    float* out = (float*)d_out;

    zero_out_kernel<<<(OUT_ELEMS/4 + 255)/256, 256>>>((float4*)out);
    scatter_kernel<<<NBLOCKS, 256>>>(x, intr, pose, out);
}

// round 11
// speedup vs baseline: 2.2596x; 1.0287x over previous
#include <cuda_runtime.h>
#include <cstdint>

// Problem constants (FrustumPooling_721554506291)
#define Bb 2
#define Nn 4
#define Dd 48
#define Hh 28
#define Ww 60
#define Cc 64
#define NX 192
#define NY 192
#define PLANE (NY*NX)                  // 36864
#define OUT_ELEMS (Bb*Cc*PLANE)        // 4,718,592 floats
#define NBLOCKS (Bb*Dd*Ww)             // 5760 columns, one block each
#define NPAIRS (Nn*Hh)                 // 112 (n,h) vectors per column
#define NHW 16                         // half-warps per block
#define PER_HW (NPAIRS/NHW)            // 7 pairs per half-warp
#define NSLOT (NHW*2)                  // 32 merge slots

static_assert(NPAIRS % NHW == 0, "pairs must split across half-warps");

// ---------------------------------------------------------------------------
// Zero the output (float4 stores); harness poisons d_out.
// ---------------------------------------------------------------------------
__global__ void zero_out_kernel(float4* __restrict__ o)
{
    int i = blockIdx.x * blockDim.x + threadIdx.x;
    if (i < OUT_ELEMS/4)
        o[i] = make_float4(0.f, 0.f, 0.f, 0.f);
}

__device__ __forceinline__ void red1(float* addr, float v)
{
    asm volatile("red.global.add.f32 [%0], %1;" :: "l"(addr), "f"(v) : "memory");
}

__device__ __forceinline__ void acc4(float4& a, const float4& b)
{
    a.x += b.x; a.y += b.y; a.z += b.z; a.w += b.w;
}

// Spill flush: 4 scalar reds (channel stride = PLANE in [b][c][y][x] layout)
__device__ __forceinline__ void flush4(float* __restrict__ outp, float4 a)
{
    red1(outp,           a.x);
    red1(outp +   PLANE, a.y);
    red1(outp + 2*PLANE, a.z);
    red1(outp + 3*PLANE, a.w);
}

// ---------------------------------------------------------------------------
// Column scatter, block-per-(b,d,w):
//   Setup:   8 threads build combine = rots @ inv(K) in smem.
//   Phase A: 112 threads compute (cell, x-offset) per (n,h) pair -> smem.
//   Phase B: 16 half-warps x 7 contiguous pairs; lane owns 4 channels
//            (one LDG.128 per kept pair). ALL loads issued before the merge
//            chain (register array, full unroll) so MLP ~7 hides DRAM latency.
//            2 register (run,acc) slots per thread absorb run changes.
//   Merge:   32 slots -> smem; fast path (all kept runs equal) issues ONE
//            red set per block; generic dedup fallback stays correct.
// ---------------------------------------------------------------------------
__global__ void __launch_bounds__(256)
scatter_kernel(const float* __restrict__ x,
               const float* __restrict__ intr,
               const float* __restrict__ pose,
               float* __restrict__ out)
{
    __shared__ float s_cm[Bb*Nn*12];
    __shared__ int2  s_pair[NPAIRS];        // (cell, xoff) per pair; cell=-1 rejected
    __shared__ int   s_run[NSLOT];
    __shared__ float s_acc[NSLOT][Cc];
    __shared__ int   s_r0, s_same;

    int tid = threadIdx.x;

    // ---- setup: 8 threads compute the combine matrices ----
    if (tid < Bb*Nn) {
        const float* K = intr + tid*9;
        const float* P = pose + tid*16;

        float a=K[0], b=K[1], c=K[2];
        float d=K[3], e=K[4], f=K[5];
        float g=K[6], h=K[7], ii=K[8];
        float A0 =  (e*ii - f*h);
        float A1 = -(d*ii - f*g);
        float A2 =  (d*h  - e*g);
        float det = a*A0 + b*A1 + c*A2;
        float id  = 1.0f / det;
        float inv[9];
        inv[0] = A0*id;           inv[1] = (c*h - b*ii)*id; inv[2] = (b*f - c*e)*id;
        inv[3] = A1*id;           inv[4] = (a*ii - c*g)*id; inv[5] = (c*d - a*f)*id;
        inv[6] = A2*id;           inv[7] = (b*g - a*h)*id;  inv[8] = (a*e - b*d)*id;

        float* o = s_cm + tid*12;
        #pragma unroll
        for (int r = 0; r < 3; r++) {
            #pragma unroll
            for (int col = 0; col < 3; col++) {
                o[r*3+col] = P[r*4+0]*inv[0*3+col]
                           + P[r*4+1]*inv[1*3+col]
                           + P[r*4+2]*inv[2*3+col];
            }
            o[9+r] = P[r*4+3];
        }
    }
    __syncthreads();

    // ---- column decode ----
    int gcol = blockIdx.x;
    int w  = gcol % Ww;  int t2 = gcol / Ww;
    int d  = t2 % Dd;
    int b  = t2 / Dd;

    float u  = (float)w * (479.0f/59.0f);
    float df = 2.0f + (float)d;
    float ud = u * df;

    // ---- Phase A: one thread per (n,h) pair ----
    if (tid < NPAIRS) {
        int n = tid / Hh;
        int h = tid - n*Hh;

        const float* cm = s_cm + (b*Nn + n)*12;
        float vd = ((float)h * (223.0f/27.0f)) * df;
        float g0 = cm[0]*ud + cm[2]*df + cm[9]  + cm[1]*vd;
        float g1 = cm[3]*ud + cm[5]*df + cm[10] + cm[4]*vd;
        float g2 = cm[6]*ud + cm[8]*df + cm[11] + cm[7]*vd;

        int gx = (int)(g0 * 4.0f + 96.0f);   // trunc-toward-zero == astype(int32)
        int gy = (int)(g1 * 4.0f + 96.0f);
        int gz = (int)((g2 + 10.0f) / 20.0f);

        bool kept = ((unsigned)gx < NX) && ((unsigned)gy < NY) && (gz == 0);
        int cell = kept ? (gy*NX + gx) : -1;
        int xoff = (n*(Dd*Hh*Ww) + h*Ww) * Cc;
        s_pair[tid] = make_int2(cell, xoff);
    }
    __syncthreads();

    // ---- Phase B: half-warp per 7-pair chunk, lane owns 4 channels ----
    int hw = tid >> 4;            // 0..15
    int l4 = (tid & 15) * 4;      // channel base

    const float* xcol = x + ((size_t)(b*Nn)*Dd + d) * (Hh*Ww*Cc)
                          + w*Cc + l4;
    float* outbase = out + ((size_t)b*Cc + l4) * PLANE;

    // Batch: read pairs + issue all kept loads before any merging
    int    cell[PER_HW];
    float4 val[PER_HW];
    #pragma unroll
    for (int j = 0; j < PER_HW; j++) {
        int2 pr = s_pair[hw*PER_HW + j];
        cell[j] = pr.x;
        if (pr.x >= 0)
            val[j] = *reinterpret_cast<const float4*>(xcol + pr.y);
    }

    // 2-slot run merge (spill path keeps generality)
    int    r0 = -1, r1 = -1;
    float4 a0, a1;
    #pragma unroll
    for (int j = 0; j < PER_HW; j++) {
        if (cell[j] >= 0) {
            if      (cell[j] == r0) acc4(a0, val[j]);
            else if (cell[j] == r1) acc4(a1, val[j]);
            else if (r0 < 0)        { r0 = cell[j]; a0 = val[j]; }
            else if (r1 < 0)        { r1 = cell[j]; a1 = val[j]; }
            else {                  // spill oldest (rare)
                flush4(outbase + r0, a0);
                r0 = cell[j]; a0 = val[j];
            }
        }
    }

    // ---- publish slots ----
    if ((tid & 15) == 0) {
        s_run[hw*2]   = r0;
        s_run[hw*2+1] = r1;
    }
    s_acc[hw*2][l4]     = a0.x;  s_acc[hw*2][l4+1]   = a0.y;
    s_acc[hw*2][l4+2]   = a0.z;  s_acc[hw*2][l4+3]   = a0.w;
    s_acc[hw*2+1][l4]   = a1.x;  s_acc[hw*2+1][l4+1] = a1.y;
    s_acc[hw*2+1][l4+2] = a1.z;  s_acc[hw*2+1][l4+3] = a1.w;
    __syncthreads();

    // ---- scan runs (thread 0) ----
    if (tid == 0) {
        int r = -1, same = 1;
        #pragma unroll
        for (int e = 0; e < NSLOT; e++) {
            int re = s_run[e];
            if (re >= 0) {
                if (r < 0) r = re;
                else if (re != r) same = 0;
            }
        }
        s_r0 = r; s_same = same;
    }
    __syncthreads();

    int rr = s_r0;
    if (rr < 0) return;                       // fully rejected column

    if (s_same) {
        // fast path: one red per channel for the whole block
        if (tid < Cc) {
            float sum = 0.f;
            #pragma unroll
            for (int e = 0; e < NSLOT; e++)
                if (s_run[e] >= 0) sum += s_acc[e][tid];
            red1(out + ((size_t)b*Cc + tid)*PLANE + rr, sum);
        }
    } else {
        // generic dedup fallback (rare)
        if (tid < Cc) {
            float* outc = out + ((size_t)b*Cc + tid)*PLANE;
            for (int e = 0; e < NSLOT; e++) {
                int r = s_run[e];
                if (r < 0) continue;
                bool first = true;
                for (int f = 0; f < e; f++)
                    if (s_run[f] == r) { first = false; break; }
                if (!first) continue;
                float sum = s_acc[e][tid];
                for (int f = e+1; f < NSLOT; f++)
                    if (s_run[f] == r) sum += s_acc[f][tid];
                red1(outc + r, sum);
            }
        }
    }
}

// ---------------------------------------------------------------------------
extern "C" void kernel_launch(void* const* d_in, const int* in_sizes, int n_in,
                              void* d_out, int out_size)
{
    const float* x    = (const float*)d_in[0];
    const float* intr = (const float*)d_in[1];
    const float* pose = (const float*)d_in[2];
    float* out = (float*)d_out;

    zero_out_kernel<<<(OUT_ELEMS/4 + 255)/256, 256>>>((float4*)out);
    scatter_kernel<<<NBLOCKS, 256>>>(x, intr, pose, out);
}

// round 12
// speedup vs baseline: 3.1988x; 1.4157x over previous
#include <cuda_runtime.h>
#include <cstdint>

// Problem constants (FrustumPooling_721554506291)
#define Bb 2
#define Nn 4
#define Dd 48
#define Hh 28
#define Ww 60
#define Cc 64
#define NX 192
#define NY 192
#define PLANE (NY*NX)                  // 36864
#define OUT_ELEMS (Bb*Cc*PLANE)        // 4,718,592 floats
#define NBLOCKS (Bb*Dd*Ww)             // 5760 columns, one block each
#define NPAIRS (Nn*Hh)                 // 112 (n,h) vectors per column
#define NHW 16                         // half-warps per block
#define PER_HW (NPAIRS/NHW)            // 7 pairs per half-warp (slow path)
#define NSLOT (NHW*2)                  // 32 merge slots (slow path)

static_assert(NPAIRS % NHW == 0, "pairs must split across half-warps");

// Per-(b,n): combine[9] followed by trans[3] — computed once in zero kernel.
__device__ float g_combine[Bb*Nn*12];

// ---------------------------------------------------------------------------
// Zero output + (block 0) compute combine = rots @ inv(K).
// grid*block == OUT_ELEMS/4 exactly.
// ---------------------------------------------------------------------------
__global__ void zero_setup_kernel(float4* __restrict__ o,
                                  const float* __restrict__ intr,
                                  const float* __restrict__ pose)
{
    int i = blockIdx.x * blockDim.x + threadIdx.x;
    if (i < OUT_ELEMS/4)
        o[i] = make_float4(0.f, 0.f, 0.f, 0.f);

    if (blockIdx.x == 0 && threadIdx.x < Bb*Nn) {
        int t = threadIdx.x;
        const float* K = intr + t*9;
        const float* P = pose + t*16;

        float a=K[0], b=K[1], c=K[2];
        float d=K[3], e=K[4], f=K[5];
        float g=K[6], h=K[7], ii=K[8];
        float A0 =  (e*ii - f*h);
        float A1 = -(d*ii - f*g);
        float A2 =  (d*h  - e*g);
        float det = a*A0 + b*A1 + c*A2;
        float id  = 1.0f / det;
        float inv[9];
        inv[0] = A0*id;           inv[1] = (c*h - b*ii)*id; inv[2] = (b*f - c*e)*id;
        inv[3] = A1*id;           inv[4] = (a*ii - c*g)*id; inv[5] = (c*d - a*f)*id;
        inv[6] = A2*id;           inv[7] = (b*g - a*h)*id;  inv[8] = (a*e - b*d)*id;

        float* out = g_combine + t*12;
        #pragma unroll
        for (int r = 0; r < 3; r++) {
            #pragma unroll
            for (int col = 0; col < 3; col++) {
                out[r*3+col] = P[r*4+0]*inv[0*3+col]
                             + P[r*4+1]*inv[1*3+col]
                             + P[r*4+2]*inv[2*3+col];
            }
            out[9+r] = P[r*4+3];
        }
    }
}

__device__ __forceinline__ void red1(float* addr, float v)
{
    asm volatile("red.global.add.f32 [%0], %1;" :: "l"(addr), "f"(v) : "memory");
}

__device__ __forceinline__ void acc4(float4& a, const float4& b)
{
    a.x += b.x; a.y += b.y; a.z += b.z; a.w += b.w;
}

__device__ __forceinline__ void flush4(float* __restrict__ outp, float4 a)
{
    red1(outp,           a.x);
    red1(outp +   PLANE, a.y);
    red1(outp + 2*PLANE, a.z);
    red1(outp + 3*PLANE, a.w);
}

// ---------------------------------------------------------------------------
// Column scatter, block-per-(b,d,w):
//   Phase A: 112 threads compute cell per (n,h) pair; kept pairs append their
//            x-offset to a compact smem list; all-same-cell detected via
//            smem atomics (generic, no input assumption).
//   Fast path (all kept pairs -> one cell): half-warps stride the compact
//            list, pure LDG.128 + FADD accumulate (no merge ALU, no work for
//            rejected pairs), block-reduce in smem, ONE red per channel.
//   Slow path: R11 2-slot merge + generic dedup (correct for any geometry).
// ---------------------------------------------------------------------------
__global__ void __launch_bounds__(256)
scatter_kernel(const float* __restrict__ x, float* __restrict__ out)
{
    __shared__ float s_cm[Bb*Nn*12];
    __shared__ int   s_cell[NPAIRS];        // cell per pair (-1 rejected)
    __shared__ int   s_pxoff[NPAIRS];       // x offset per pair (slow path)
    __shared__ int   s_cxoff[NPAIRS];       // compact kept x offsets (fast path)
    __shared__ int   s_run[NSLOT];
    __shared__ float s_acc[NSLOT][Cc];
    __shared__ int   s_cnt, s_same, s_first;

    int tid = threadIdx.x;
    if (tid < Bb*Nn*12) s_cm[tid] = g_combine[tid];
    if (tid == 0) { s_cnt = 0; s_same = 1; s_first = -1; }
    __syncthreads();

    // ---- column decode ----
    int gcol = blockIdx.x;
    int w  = gcol % Ww;  int t2 = gcol / Ww;
    int d  = t2 % Dd;
    int b  = t2 / Dd;

    float u  = (float)w * (479.0f/59.0f);
    float df = 2.0f + (float)d;
    float ud = u * df;

    // ---- Phase A: one thread per (n,h) pair ----
    if (tid < NPAIRS) {
        int n = tid / Hh;
        int h = tid - n*Hh;

        const float* cm = s_cm + (b*Nn + n)*12;
        float vd = ((float)h * (223.0f/27.0f)) * df;
        float g0 = cm[0]*ud + cm[2]*df + cm[9]  + cm[1]*vd;
        float g1 = cm[3]*ud + cm[5]*df + cm[10] + cm[4]*vd;
        float g2 = cm[6]*ud + cm[8]*df + cm[11] + cm[7]*vd;

        int gx = (int)(g0 * 4.0f + 96.0f);   // trunc-toward-zero == astype(int32)
        int gy = (int)(g1 * 4.0f + 96.0f);
        int gz = (int)((g2 + 10.0f) / 20.0f);

        bool kept = ((unsigned)gx < NX) && ((unsigned)gy < NY) && (gz == 0);
        int cell = kept ? (gy*NX + gx) : -1;
        int xoff = (n*(Dd*Hh*Ww) + h*Ww) * Cc;
        s_cell[tid]  = cell;
        s_pxoff[tid] = xoff;
        if (kept) {
            int old = atomicCAS(&s_first, -1, cell);
            if (old != -1 && old != cell) s_same = 0;
            int p = atomicAdd(&s_cnt, 1);
            s_cxoff[p] = xoff;
        }
    }
    __syncthreads();

    int cnt = s_cnt;
    if (cnt == 0) return;                 // empty column (uniform)

    int hw = tid >> 4;                    // 0..15
    int l4 = (tid & 15) * 4;              // channel base

    const float* xcol = x + ((size_t)(b*Nn)*Dd + d) * (Hh*Ww*Cc)
                          + w*Cc + l4;

    if (s_same) {
        // ---- fast path: pure accumulate over compact list ----
        float4 a0 = make_float4(0.f,0.f,0.f,0.f);
        float4 a1 = make_float4(0.f,0.f,0.f,0.f);
        int i = hw;
        for (; i + NHW < cnt; i += 2*NHW) {
            float4 v0 = *reinterpret_cast<const float4*>(xcol + s_cxoff[i]);
            float4 v1 = *reinterpret_cast<const float4*>(xcol + s_cxoff[i+NHW]);
            acc4(a0, v0);
            acc4(a1, v1);
        }
        if (i < cnt)
            acc4(a0, *reinterpret_cast<const float4*>(xcol + s_cxoff[i]));
        acc4(a0, a1);

        s_acc[hw][l4]   = a0.x;  s_acc[hw][l4+1] = a0.y;
        s_acc[hw][l4+2] = a0.z;  s_acc[hw][l4+3] = a0.w;
        __syncthreads();

        if (tid < Cc) {
            float sum = 0.f;
            #pragma unroll
            for (int e = 0; e < NHW; e++) sum += s_acc[e][tid];
            red1(out + ((size_t)b*Cc + tid)*PLANE + s_first, sum);
        }
        return;
    }

    // ---- slow path: 2-slot merge per half-warp + generic dedup ----
    float* outbase = out + ((size_t)b*Cc + l4) * PLANE;

    int    r0 = -1, r1 = -1;
    float4 a0, a1;
    #pragma unroll
    for (int j = 0; j < PER_HW; j++) {
        int idx  = hw*PER_HW + j;
        int cell = s_cell[idx];
        if (cell >= 0) {
            float4 val = *reinterpret_cast<const float4*>(xcol + s_pxoff[idx]);
            if      (cell == r0) acc4(a0, val);
            else if (cell == r1) acc4(a1, val);
            else if (r0 < 0)     { r0 = cell; a0 = val; }
            else if (r1 < 0)     { r1 = cell; a1 = val; }
            else {               // spill oldest (rare)
                flush4(outbase + r0, a0);
                r0 = cell; a0 = val;
            }
        }
    }

    if ((tid & 15) == 0) {
        s_run[hw*2]   = r0;
        s_run[hw*2+1] = r1;
    }
    s_acc[hw*2][l4]     = a0.x;  s_acc[hw*2][l4+1]   = a0.y;
    s_acc[hw*2][l4+2]   = a0.z;  s_acc[hw*2][l4+3]   = a0.w;
    s_acc[hw*2+1][l4]   = a1.x;  s_acc[hw*2+1][l4+1] = a1.y;
    s_acc[hw*2+1][l4+2] = a1.z;  s_acc[hw*2+1][l4+3] = a1.w;
    __syncthreads();

    if (tid < Cc) {
        float* outc = out + ((size_t)b*Cc + tid)*PLANE;
        for (int e = 0; e < NSLOT; e++) {
            int r = s_run[e];
            if (r < 0) continue;
            bool first = true;
            for (int f = 0; f < e; f++)
                if (s_run[f] == r) { first = false; break; }
            if (!first) continue;
            float sum = s_acc[e][tid];
            for (int f = e+1; f < NSLOT; f++)
                if (s_run[f] == r) sum += s_acc[f][tid];
            red1(outc + r, sum);
        }
    }
}

// ---------------------------------------------------------------------------
extern "C" void kernel_launch(void* const* d_in, const int* in_sizes, int n_in,
                              void* d_out, int out_size)
{
    const float* x    = (const float*)d_in[0];
    const float* intr = (const float*)d_in[1];
    const float* pose = (const float*)d_in[2];
    float* out = (float*)d_out;

    zero_setup_kernel<<<OUT_ELEMS/4/256, 256>>>((float4*)out, intr, pose);
    scatter_kernel<<<NBLOCKS, 256>>>(x, out);
}